// round 14
// baseline (speedup 1.0000x reference)
#include <cuda_runtime.h>
#include <cuda_fp16.h>
#include <cstdint>

#define B 16
#define S 2048
#define D 64
#define TR 32
#define TC 128
#define NTH 512
#define KP 72          // halves pitch for K/V smem rows (144 B)
#define PP 2056        // halves pitch for dense orig-order P rows (4112 B)

// ---- smem byte offsets ----
#define OFF_PH    0                      // 32 x 2056 half = 131584 (orig-order dense)
#define OFF_STAGE 131584                 // 3 stages x 18432 (phase1: K; phase2: V)
#define STG_STRIDE 18432
#define OFF_QH    186880                 // 4608
#define OFF_CIDX  191488                 // 8192 (compact -> orig)
#define OFF_WSUM  199680                 // 128
#define OFF_INV   199808                 // 128
#define OFF_ORIG  199936                 // 128
#define SMEM_BYTES 200064

// log2(e)/8 : folds the 1/sqrt(64) score scale AND exp->exp2 conversion into Q
#define QSCALE 0.18033688011112042f

// ---------- device scratch ----------
__device__ int g_cidx[B][S];
__device__ int g_midx[B][S];
__device__ int g_pinv[B][S];
__device__ int g_ccnt[B];
__device__ __half g_kh[(size_t)B * S * D];   // compact order
__device__ __half g_vh[(size_t)B * S * D];   // ORIG order, masked rows zeroed

// ---------- asm helpers ----------
__device__ __forceinline__ void ldsm4(uint32_t& r0, uint32_t& r1, uint32_t& r2,
                                      uint32_t& r3, uint32_t a) {
    asm volatile("ldmatrix.sync.aligned.m8n8.x4.shared.b16 {%0,%1,%2,%3}, [%4];"
                 : "=r"(r0), "=r"(r1), "=r"(r2), "=r"(r3) : "r"(a));
}
__device__ __forceinline__ void ldsm2t(uint32_t& r0, uint32_t& r1, uint32_t a) {
    asm volatile("ldmatrix.sync.aligned.m8n8.x2.trans.shared.b16 {%0,%1}, [%2];"
                 : "=r"(r0), "=r"(r1) : "r"(a));
}
__device__ __forceinline__ void mma16816(float* d, uint32_t a0, uint32_t a1,
                                         uint32_t a2, uint32_t a3,
                                         uint32_t b0, uint32_t b1) {
    asm volatile(
        "mma.sync.aligned.m16n8k16.row.col.f32.f16.f16.f32 "
        "{%0,%1,%2,%3},{%4,%5,%6,%7},{%8,%9},{%0,%1,%2,%3};"
        : "+f"(d[0]), "+f"(d[1]), "+f"(d[2]), "+f"(d[3])
        : "r"(a0), "r"(a1), "r"(a2), "r"(a3), "r"(b0), "r"(b1));
}
__device__ __forceinline__ float ex2(float x) {
    float r;
    asm("ex2.approx.f32 %0, %1;" : "=f"(r) : "f"(x));
    return r;
}
__device__ __forceinline__ void cpa16(uint32_t saddr, const void* g) {
    asm volatile("cp.async.cg.shared.global [%0], [%1], 16;" :: "r"(saddr), "l"(g)
                 : "memory");
}
__device__ __forceinline__ void cpcommit() {
    asm volatile("cp.async.commit_group;" ::: "memory");
}
__device__ __forceinline__ void cpwait1() {
    asm volatile("cp.async.wait_group 1;" ::: "memory");
}
__device__ __forceinline__ void cpwait0() {
    asm volatile("cp.async.wait_group 0;" ::: "memory");
}
// streaming store (evict-first): output never re-read; keep K/V resident in L2
__device__ __forceinline__ void stcs4(float4* p, float4 v) {
    asm volatile("st.global.cs.v4.f32 [%0], {%1,%2,%3,%4};"
                 :: "l"(p), "f"(v.x), "f"(v.y), "f"(v.z), "f"(v.w) : "memory");
}

// ---------- mask build ----------
__global__ void build_mask_kernel(const void* mptr) {
    const int b = blockIdx.x;
    const int tid = threadIdx.x;
    __shared__ int warpTot[8];
    __shared__ int okInt, okFlt;
    const unsigned char* pb = (const unsigned char*)mptr;
    if (tid == 0) { okInt = 1; okFlt = 1; }
    __syncthreads();
    {
        unsigned char b0 = pb[4*tid], b1 = pb[4*tid+1], b2 = pb[4*tid+2], b3 = pb[4*tid+3];
        bool gi = (b0 <= 1 && b1 == 0 && b2 == 0 && b3 == 0);
        bool zf = (b0 == 0 && b1 == 0 && b2 == 0 && b3 == 0);
        bool of = (b0 == 0 && b1 == 0 && b2 == 0x80 && b3 == 0x3f);
        if (!gi) atomicExch(&okInt, 0);
        if (!(zf || of)) atomicExch(&okFlt, 0);
    }
    __syncthreads();
    const int mode = okInt ? 1 : (okFlt ? 2 : 0);
    unsigned char mloc[8];
    int cnt = 0;
    #pragma unroll
    for (int k = 0; k < 8; k++) {
        int i = b * S + tid * 8 + k;
        unsigned char m;
        if (mode == 1)      m = (((const int*)mptr)[i] != 0);
        else if (mode == 2) m = (((const float*)mptr)[i] != 0.0f);
        else                m = (pb[i] != 0);
        mloc[k] = m;
        cnt += (m == 0);
    }
    int lane = tid & 31, w = tid >> 5;
    int x = cnt;
    #pragma unroll
    for (int off = 1; off < 32; off <<= 1) {
        int y = __shfl_up_sync(0xffffffffu, x, off);
        if (lane >= off) x += y;
    }
    if (lane == 31) warpTot[w] = x;
    __syncthreads();
    int wOff = 0;
    for (int ww = 0; ww < w; ww++) wOff += warpTot[ww];
    int pos = wOff + x - cnt;
    #pragma unroll
    for (int k = 0; k < 8; k++) {
        int idx = tid * 8 + k;
        if (!mloc[k]) {
            g_cidx[b][pos] = idx;
            g_pinv[b][idx] = pos;
            pos++;
        } else {
            g_midx[b][idx - pos] = idx;
            g_pinv[b][idx] = -1;
        }
    }
    if (tid == 255) g_ccnt[b] = pos;
}

// ---------- preprocess K -> fp16 in COMPACT order ----------
__global__ void preprocess_k_kernel(const float* __restrict__ K) {
    const int b = blockIdx.y;
    const int tid = threadIdx.x;
    const int cc = blockIdx.x * 64 + (tid >> 2);
    const int qd = (tid & 3) * 16;
    const int nc = g_ccnt[b];
    __half* kh = g_kh + ((size_t)b * S + cc) * D + qd;
    if (cc < nc) {
        int orig = g_cidx[b][cc];
        const float4* kp = (const float4*)(K + ((size_t)b * S + orig) * D + qd);
        #pragma unroll
        for (int j = 0; j < 4; j++) {
            float4 kv = kp[j];
            ((__half2*)(kh + j * 4))[0] = __floats2half2_rn(kv.x, kv.y);
            ((__half2*)(kh + j * 4))[1] = __floats2half2_rn(kv.z, kv.w);
        }
    } else {
        uint2 z = {0u, 0u};
        #pragma unroll
        for (int j = 0; j < 4; j++) *(uint2*)(kh + j * 4) = z;
    }
}

// ---------- preprocess V -> fp16 in ORIG order (masked rows zeroed) ----------
__global__ void preprocess_v_kernel(const float* __restrict__ V) {
    const int b = blockIdx.y;
    const int tid = threadIdx.x;
    const int row = blockIdx.x * 64 + (tid >> 2);   // orig row
    const int qd = (tid & 3) * 16;
    __half* vh = g_vh + ((size_t)b * S + row) * D + qd;
    if (g_pinv[b][row] >= 0) {
        const float4* vp = (const float4*)(V + ((size_t)b * S + row) * D + qd);
        #pragma unroll
        for (int j = 0; j < 4; j++) {
            float4 vv = vp[j];
            ((__half2*)(vh + j * 4))[0] = __floats2half2_rn(vv.x, vv.y);
            ((__half2*)(vh + j * 4))[1] = __floats2half2_rn(vv.z, vv.w);
        }
    } else {
        uint2 z = {0u, 0u};
        #pragma unroll
        for (int j = 0; j < 4; j++) *(uint2*)(vh + j * 4) = z;
    }
}

// ---------- main attention kernel ----------
extern __shared__ char smem[];

__global__ __launch_bounds__(NTH, 1)
void attn_kernel(const float* __restrict__ Q, float* __restrict__ out) {
    const int b = blockIdx.y;
    const int ncols = g_ccnt[b];
    const int nActive = (ncols + TR - 1) / TR;
    const int tid = threadIdx.x;

    // ---- zero-fill branch: masked rows ----
    if ((int)blockIdx.x >= nActive) {
        const int nmask = S - ncols;
        const int m0 = ((int)blockIdx.x - nActive) * TR;
        const int r = tid >> 4, tg = tid & 15;
        if (m0 + r >= nmask) return;
        const int row = g_midx[b][m0 + r];
        float4 z = {0.f, 0.f, 0.f, 0.f};
        float4* arow = (float4*)(out + (size_t)B * S * D + ((size_t)b * S + row) * S);
        #pragma unroll 8
        for (int it = 0; it < 32; it++) stcs4(arow + it * 16 + tg, z);
        stcs4((float4*)(out + ((size_t)b * S + row) * D + tg * 4), z);
        return;
    }

    const int row0c = blockIdx.x * TR;
    const int nrows = min(TR, ncols - row0c);
    const int lane = tid & 31, w = tid >> 5;
    const int rg = w >> 3, cg = w & 7;
    const int nt = (ncols + TC - 1) / TC;     // compact tiles (QK)
    const int ntv = S / TC;                   // dense tiles (PV) = 16

    __half* sPh  = (__half*)(smem + OFF_PH);
    int*    sCid = (int*)(smem + OFF_CIDX);
    float*  sWsum= (float*)(smem + OFF_WSUM);
    float*  sInv = (float*)(smem + OFF_INV);
    int*    sOrig= (int*)(smem + OFF_ORIG);
    const uint32_t smemBase = (uint32_t)__cvta_generic_to_shared(smem);

    const __half* khB = g_kh + (size_t)b * S * D;
    const __half* vhB = g_vh + (size_t)b * S * D;

    // ---- phase-1 prologue: prefetch K tiles 0,1 ----
    {
        const int j = tid >> 2, c = (tid & 3) * 2;
        #pragma unroll
        for (int t = 0; t < 2; t++) {
            if (t < nt) {
                uint32_t stg = smemBase + OFF_STAGE + t * STG_STRIDE
                             + (uint32_t)((j * KP + c * 8) * 2);
                size_t gofs = (size_t)(t * TC + j) * D + c * 8;
                cpa16(stg, khB + gofs);
                cpa16(stg + 16, khB + gofs + 8);
            }
            cpcommit();
        }
    }

    if (tid < TR) sWsum[tid] = 0.f;
    ((int4*)sCid)[tid] = ((const int4*)&g_cidx[b][0])[tid];

    // ---- zero dense P buffer (131584 B = 8224 uint4) ----
    {
        uint4 z = {0u, 0u, 0u, 0u};
        uint4* p = (uint4*)sPh;
        for (int i = tid; i < 8224; i += NTH) p[i] = z;
    }

    // ---- Q load -> fp16 (pre-scaled by log2e/8) ----
    {
        int r = tid >> 4, f = tid & 15;
        float4 q = {0.f, 0.f, 0.f, 0.f};
        if (r < nrows) {
            int orig = g_cidx[b][row0c + r];
            if (f == 0) sOrig[r] = orig;
            q = ((const float4*)(Q + ((size_t)b * S + orig) * D))[f];
            q.x *= QSCALE; q.y *= QSCALE; q.z *= QSCALE; q.w *= QSCALE;
        }
        __half2* dh = (__half2*)(smem + OFF_QH + ((size_t)r * KP + f * 4) * 2);
        dh[0] = __floats2half2_rn(q.x, q.y);
        dh[1] = __floats2half2_rn(q.z, q.w);
    }
    __syncthreads();

    // ---- Q fragments to registers ----
    uint32_t qh[4][4];
    {
        const uint32_t aQoff =
            (uint32_t)(((rg * 16 + (lane & 15)) * KP + ((lane >> 4) << 3)) * 2);
        #pragma unroll
        for (int kk = 0; kk < 4; kk++)
            ldsm4(qh[kk][0], qh[kk][1], qh[kk][2], qh[kk][3],
                  smemBase + OFF_QH + aQoff + kk * 32);
    }

    const uint32_t bKoff =
        (uint32_t)(((cg * 16 + (lane & 7) + ((lane >> 4) << 3)) * KP
                    + (((lane >> 3) & 1) << 3)) * 2);
    const int rowE = rg * 16 + (lane >> 2);
    const int colE = cg * 16 + ((lane & 3) << 1);

    float sumLo = 0.f, sumHi = 0.f;

    // ================= PHASE 1: QK + deferred-exp SCATTER epilogue =============
    {
        float p0[4], p1[4];
        int cbPrev = 0;
        for (int i = 0; i < nt; i++) {
            const int ct = i * TC;
            const uint32_t stg = smemBase + OFF_STAGE + (uint32_t)((i % 3) * STG_STRIDE);
            cpwait1();
            __syncthreads();

            float c0[4] = {0.f, 0.f, 0.f, 0.f};
            float c1[4] = {0.f, 0.f, 0.f, 0.f};
            #pragma unroll
            for (int kk = 0; kk < 4; kk++) {
                uint32_t bh0, bh1, bh2, bh3;
                ldsm4(bh0, bh1, bh2, bh3, stg + bKoff + kk * 32);
                mma16816(c0, qh[kk][0], qh[kk][1], qh[kk][2], qh[kk][3], bh0, bh1);
                mma16816(c1, qh[kk][0], qh[kk][1], qh[kk][2], qh[kk][3], bh2, bh3);
            }
            if (i + 2 < nt) {
                const int j = tid >> 2, cch = (tid & 3) * 2;
                uint32_t sdst = smemBase + OFF_STAGE
                              + (uint32_t)(((i + 2) % 3) * STG_STRIDE)
                              + (uint32_t)((j * KP + cch * 8) * 2);
                size_t gofs = (size_t)((i + 2) * TC + j) * D + cch * 8;
                cpa16(sdst, khB + gofs);
                cpa16(sdst + 16, khB + gofs + 8);
            }
            cpcommit();
            if (i > 0) {
                const int cb = cbPrev;
                if (cb < ncols) {
                    float e0 = ex2(p0[0]), e2 = ex2(p0[2]);
                    sumLo += e0; sumHi += e2;
                    int oc = sCid[cb];
                    sPh[rowE * PP + oc]       = __float2half_rn(e0);
                    sPh[(rowE + 8) * PP + oc] = __float2half_rn(e2);
                }
                if (cb + 1 < ncols) {
                    float e1 = ex2(p0[1]), e3 = ex2(p0[3]);
                    sumLo += e1; sumHi += e3;
                    int oc = sCid[cb + 1];
                    sPh[rowE * PP + oc]       = __float2half_rn(e1);
                    sPh[(rowE + 8) * PP + oc] = __float2half_rn(e3);
                }
                if (cb + 8 < ncols) {
                    float e4 = ex2(p1[0]), e6 = ex2(p1[2]);
                    sumLo += e4; sumHi += e6;
                    int oc = sCid[cb + 8];
                    sPh[rowE * PP + oc]       = __float2half_rn(e4);
                    sPh[(rowE + 8) * PP + oc] = __float2half_rn(e6);
                }
                if (cb + 9 < ncols) {
                    float e5 = ex2(p1[1]), e7 = ex2(p1[3]);
                    sumLo += e5; sumHi += e7;
                    int oc = sCid[cb + 9];
                    sPh[rowE * PP + oc]       = __float2half_rn(e5);
                    sPh[(rowE + 8) * PP + oc] = __float2half_rn(e7);
                }
            }
            #pragma unroll
            for (int j = 0; j < 4; j++) { p0[j] = c0[j]; p1[j] = c1[j]; }
            cbPrev = ct + colE;
        }
        {
            const int cb = cbPrev;
            if (cb < ncols) {
                float e0 = ex2(p0[0]), e2 = ex2(p0[2]);
                sumLo += e0; sumHi += e2;
                int oc = sCid[cb];
                sPh[rowE * PP + oc]       = __float2half_rn(e0);
                sPh[(rowE + 8) * PP + oc] = __float2half_rn(e2);
            }
            if (cb + 1 < ncols) {
                float e1 = ex2(p0[1]), e3 = ex2(p0[3]);
                sumLo += e1; sumHi += e3;
                int oc = sCid[cb + 1];
                sPh[rowE * PP + oc]       = __float2half_rn(e1);
                sPh[(rowE + 8) * PP + oc] = __float2half_rn(e3);
            }
            if (cb + 8 < ncols) {
                float e4 = ex2(p1[0]), e6 = ex2(p1[2]);
                sumLo += e4; sumHi += e6;
                int oc = sCid[cb + 8];
                sPh[rowE * PP + oc]       = __float2half_rn(e4);
                sPh[(rowE + 8) * PP + oc] = __float2half_rn(e6);
            }
            if (cb + 9 < ncols) {
                float e5 = ex2(p1[1]), e7 = ex2(p1[3]);
                sumLo += e5; sumHi += e7;
                int oc = sCid[cb + 9];
                sPh[rowE * PP + oc]       = __float2half_rn(e5);
                sPh[(rowE + 8) * PP + oc] = __float2half_rn(e7);
            }
        }
    }

    // ---- row sums -> sInv ----
    sumLo += __shfl_xor_sync(0xffffffffu, sumLo, 1);
    sumLo += __shfl_xor_sync(0xffffffffu, sumLo, 2);
    sumHi += __shfl_xor_sync(0xffffffffu, sumHi, 1);
    sumHi += __shfl_xor_sync(0xffffffffu, sumHi, 2);
    if ((lane & 3) == 0) {
        atomicAdd(&sWsum[rowE], sumLo);
        atomicAdd(&sWsum[rowE + 8], sumHi);
    }
    __syncthreads();
    if (tid < TR) {
        float t = sWsum[tid];
        sInv[tid] = (t > 0.f) ? (1.f / t) : 0.f;
    }
    __syncthreads();

    // ================= PHASE 2: vectorized WB then dense PV ====================
    cpwait0();
    // V prologue: prefetch dense tiles 0,1
    {
        const int j = tid >> 2, c0 = (tid & 3) * 2;
        #pragma unroll
        for (int t = 0; t < 2; t++) {
            uint32_t stg = smemBase + OFF_STAGE + t * STG_STRIDE
                         + (uint32_t)((j * KP + c0 * 8) * 2);
            size_t gofs = (size_t)(t * TC + j) * D + c0 * 8;
            cpa16(stg, vhB + gofs);
            cpa16(stg + 16, vhB + gofs + 8);
            cpcommit();
        }
    }

    // ---- attn writeback: ALL 16 warps, 2 rows each, fully vectorized ----
    #pragma unroll
    for (int rr = 0; rr < 2; rr++) {
        const int r = w * 2 + rr;
        if (r >= nrows) continue;
        const float inv = sInv[r];
        const int orig = sOrig[r];
        const uint4* src = (const uint4*)&sPh[r * PP];
        float4* dst = (float4*)(out + (size_t)B * S * D + ((size_t)b * S + orig) * S);
        #pragma unroll 4
        for (int it = 0; it < 8; it++) {
            int idx = it * 32 + lane;          // uint4 index, 0..255
            uint4 u = src[idx];
            float2 f0 = __half22float2(*(__half2*)&u.x);
            float2 f1 = __half22float2(*(__half2*)&u.y);
            float2 f2 = __half22float2(*(__half2*)&u.z);
            float2 f3 = __half22float2(*(__half2*)&u.w);
            float4 o0 = make_float4(f0.x * inv, f0.y * inv, f1.x * inv, f1.y * inv);
            float4 o1 = make_float4(f2.x * inv, f2.y * inv, f3.x * inv, f3.y * inv);
            stcs4(dst + idx * 2, o0);
            stcs4(dst + idx * 2 + 1, o1);
        }
    }

    // ---- PV: dense orig-order, 16 tiles ----
    {
        const uint32_t bVoff = (uint32_t)(((lane & 15) * KP + cg * 8) * 2);
        const uint32_t aP =
            (uint32_t)(((rg * 16 + (lane & 15)) * PP + ((lane >> 4) << 3)) * 2);
        const int colW = cg * 8 + ((lane & 3) << 1);

        float ctx[4] = {0.f, 0.f, 0.f, 0.f};

        for (int i = 0; i < ntv; i++) {
            const int ct = i * TC;
            const uint32_t stg = smemBase + OFF_STAGE + (uint32_t)((i % 3) * STG_STRIDE);
            cpwait1();
            __syncthreads();
            #pragma unroll
            for (int ks = 0; ks < 8; ks++) {
                uint32_t a0, a1, a2, a3, b0, b1;
                ldsm2t(b0, b1, stg + bVoff + (uint32_t)(ks * 16 * KP * 2));
                ldsm4(a0, a1, a2, a3,
                      smemBase + OFF_PH + aP + (uint32_t)((ct + ks * 16) * 2));
                mma16816(ctx, a0, a1, a2, a3, b0, b1);
            }
            if (i + 2 < ntv) {
                const int j = tid >> 2, c0 = (tid & 3) * 2;
                uint32_t sdst = smemBase + OFF_STAGE
                              + (uint32_t)(((i + 2) % 3) * STG_STRIDE)
                              + (uint32_t)((j * KP + c0 * 8) * 2);
                size_t gofs = (size_t)((i + 2) * TC + j) * D + c0 * 8;
                cpa16(sdst, vhB + gofs);
                cpa16(sdst + 16, vhB + gofs + 8);
            }
            cpcommit();
        }
        // ---- context write ----
        {
            const int r0 = rg * 16 + (lane >> 2);
            if (r0 < nrows) {
                float inv = sInv[r0];
                *(float2*)(out + ((size_t)b * S + sOrig[r0]) * D + colW) =
                    make_float2(ctx[0] * inv, ctx[1] * inv);
            }
            if (r0 + 8 < nrows) {
                float inv = sInv[r0 + 8];
                *(float2*)(out + ((size_t)b * S + sOrig[r0 + 8]) * D + colW) =
                    make_float2(ctx[2] * inv, ctx[3] * inv);
            }
        }
    }
}

extern "C" void kernel_launch(void* const* d_in, const int* in_sizes, int n_in,
                              void* d_out, int out_size) {
    const float* Q = (const float*)d_in[0];
    const float* K = (const float*)d_in[1];
    const float* V = (const float*)d_in[2];
    const void*  M = d_in[3];
    float* out = (float*)d_out;

    cudaFuncSetAttribute(attn_kernel, cudaFuncAttributeMaxDynamicSharedMemorySize,
                         SMEM_BYTES);

    build_mask_kernel<<<B, 256>>>(M);
    preprocess_k_kernel<<<dim3(S / 64, B), 256>>>(K);
    preprocess_v_kernel<<<dim3(S / 64, B), 256>>>(V);
    attn_kernel<<<dim3(S / TR + 1, B), NTH, SMEM_BYTES>>>(Q, out);
}

// round 15
// speedup vs baseline: 1.3812x; 1.3812x over previous
#include <cuda_runtime.h>
#include <cuda_fp16.h>
#include <cstdint>

#define B 16
#define S 2048
#define D 64
#define TR 32
#define TC 128
#define NTH 512
#define KP 72          // halves pitch for K/V smem rows (144 B)
#define PP 2056        // halves pitch for dense compact P rows (4112 B)

// ---- smem byte offsets ----
#define OFF_PH    0                      // 32 x 2056 half = 131584
#define OFF_STAGE 131584                 // 3 stages x 18432 (phase1: K; phase2: V)
#define STG_STRIDE 18432
#define OFF_QH    186880                 // 4608
#define OFF_PINV  196096                 // 8192
#define OFF_WSUM  204288                 // 128
#define OFF_INV   204416                 // 128
#define OFF_ORIG  204544                 // 128
#define SMEM_BYTES 204672

// log2(e)/8 : folds the 1/sqrt(64) score scale AND exp->exp2 conversion into Q
#define QSCALE 0.18033688011112042f

// ---------- device scratch ----------
__device__ int g_cidx[B][S];
__device__ int g_midx[B][S];
__device__ int g_pinv[B][S];
__device__ int g_ccnt[B];
__device__ __half g_kh[(size_t)B * S * D];
__device__ __half g_vh[(size_t)B * S * D];

// ---------- asm helpers ----------
__device__ __forceinline__ void ldsm4(uint32_t& r0, uint32_t& r1, uint32_t& r2,
                                      uint32_t& r3, uint32_t a) {
    asm volatile("ldmatrix.sync.aligned.m8n8.x4.shared.b16 {%0,%1,%2,%3}, [%4];"
                 : "=r"(r0), "=r"(r1), "=r"(r2), "=r"(r3) : "r"(a));
}
__device__ __forceinline__ void ldsm2t(uint32_t& r0, uint32_t& r1, uint32_t a) {
    asm volatile("ldmatrix.sync.aligned.m8n8.x2.trans.shared.b16 {%0,%1}, [%2];"
                 : "=r"(r0), "=r"(r1) : "r"(a));
}
__device__ __forceinline__ void mma16816(float* d, uint32_t a0, uint32_t a1,
                                         uint32_t a2, uint32_t a3,
                                         uint32_t b0, uint32_t b1) {
    asm volatile(
        "mma.sync.aligned.m16n8k16.row.col.f32.f16.f16.f32 "
        "{%0,%1,%2,%3},{%4,%5,%6,%7},{%8,%9},{%0,%1,%2,%3};"
        : "+f"(d[0]), "+f"(d[1]), "+f"(d[2]), "+f"(d[3])
        : "r"(a0), "r"(a1), "r"(a2), "r"(a3), "r"(b0), "r"(b1));
}
__device__ __forceinline__ float ex2(float x) {
    float r;
    asm("ex2.approx.f32 %0, %1;" : "=f"(r) : "f"(x));
    return r;
}
__device__ __forceinline__ void cpa16(uint32_t saddr, const void* g) {
    asm volatile("cp.async.cg.shared.global [%0], [%1], 16;" :: "r"(saddr), "l"(g)
                 : "memory");
}
__device__ __forceinline__ void cpcommit() {
    asm volatile("cp.async.commit_group;" ::: "memory");
}
__device__ __forceinline__ void cpwait1() {
    asm volatile("cp.async.wait_group 1;" ::: "memory");
}
__device__ __forceinline__ void cpwait0() {
    asm volatile("cp.async.wait_group 0;" ::: "memory");
}
// streaming store (evict-first): output never re-read; keep K/V resident in L2
__device__ __forceinline__ void stcs4(float4* p, float4 v) {
    asm volatile("st.global.cs.v4.f32 [%0], {%1,%2,%3,%4};"
                 :: "l"(p), "f"(v.x), "f"(v.y), "f"(v.z), "f"(v.w) : "memory");
}

// ---------- mask build ----------
__global__ void build_mask_kernel(const void* mptr) {
    const int b = blockIdx.x;
    const int tid = threadIdx.x;
    __shared__ int warpTot[8];
    __shared__ int okInt, okFlt;
    const unsigned char* pb = (const unsigned char*)mptr;
    if (tid == 0) { okInt = 1; okFlt = 1; }
    __syncthreads();
    {
        unsigned char b0 = pb[4*tid], b1 = pb[4*tid+1], b2 = pb[4*tid+2], b3 = pb[4*tid+3];
        bool gi = (b0 <= 1 && b1 == 0 && b2 == 0 && b3 == 0);
        bool zf = (b0 == 0 && b1 == 0 && b2 == 0 && b3 == 0);
        bool of = (b0 == 0 && b1 == 0 && b2 == 0x80 && b3 == 0x3f);
        if (!gi) atomicExch(&okInt, 0);
        if (!(zf || of)) atomicExch(&okFlt, 0);
    }
    __syncthreads();
    const int mode = okInt ? 1 : (okFlt ? 2 : 0);
    unsigned char mloc[8];
    int cnt = 0;
    #pragma unroll
    for (int k = 0; k < 8; k++) {
        int i = b * S + tid * 8 + k;
        unsigned char m;
        if (mode == 1)      m = (((const int*)mptr)[i] != 0);
        else if (mode == 2) m = (((const float*)mptr)[i] != 0.0f);
        else                m = (pb[i] != 0);
        mloc[k] = m;
        cnt += (m == 0);
    }
    int lane = tid & 31, w = tid >> 5;
    int x = cnt;
    #pragma unroll
    for (int off = 1; off < 32; off <<= 1) {
        int y = __shfl_up_sync(0xffffffffu, x, off);
        if (lane >= off) x += y;
    }
    if (lane == 31) warpTot[w] = x;
    __syncthreads();
    int wOff = 0;
    for (int ww = 0; ww < w; ww++) wOff += warpTot[ww];
    int pos = wOff + x - cnt;
    #pragma unroll
    for (int k = 0; k < 8; k++) {
        int idx = tid * 8 + k;
        if (!mloc[k]) {
            g_cidx[b][pos] = idx;
            g_pinv[b][idx] = pos;
            pos++;
        } else {
            g_midx[b][idx - pos] = idx;
            g_pinv[b][idx] = -1;
        }
    }
    if (tid == 255) g_ccnt[b] = pos;
}

// ---------- preprocess K -> fp16 in compact order ----------
__global__ void preprocess_k_kernel(const float* __restrict__ K) {
    const int b = blockIdx.y;
    const int tid = threadIdx.x;
    const int cc = blockIdx.x * 64 + (tid >> 2);
    const int qd = (tid & 3) * 16;
    const int nc = g_ccnt[b];
    __half* kh = g_kh + ((size_t)b * S + cc) * D + qd;
    if (cc < nc) {
        int orig = g_cidx[b][cc];
        const float4* kp = (const float4*)(K + ((size_t)b * S + orig) * D + qd);
        #pragma unroll
        for (int j = 0; j < 4; j++) {
            float4 kv = kp[j];
            ((__half2*)(kh + j * 4))[0] = __floats2half2_rn(kv.x, kv.y);
            ((__half2*)(kh + j * 4))[1] = __floats2half2_rn(kv.z, kv.w);
        }
    } else {
        uint2 z = {0u, 0u};
        #pragma unroll
        for (int j = 0; j < 4; j++) *(uint2*)(kh + j * 4) = z;
    }
}

// ---------- preprocess V -> fp16 in compact order ----------
__global__ void preprocess_v_kernel(const float* __restrict__ V) {
    const int b = blockIdx.y;
    const int tid = threadIdx.x;
    const int cc = blockIdx.x * 64 + (tid >> 2);
    const int qd = (tid & 3) * 16;
    const int nc = g_ccnt[b];
    __half* vh = g_vh + ((size_t)b * S + cc) * D + qd;
    if (cc < nc) {
        int orig = g_cidx[b][cc];
        const float4* vp = (const float4*)(V + ((size_t)b * S + orig) * D + qd);
        #pragma unroll
        for (int j = 0; j < 4; j++) {
            float4 vv = vp[j];
            ((__half2*)(vh + j * 4))[0] = __floats2half2_rn(vv.x, vv.y);
            ((__half2*)(vh + j * 4))[1] = __floats2half2_rn(vv.z, vv.w);
        }
    } else {
        uint2 z = {0u, 0u};
        #pragma unroll
        for (int j = 0; j < 4; j++) *(uint2*)(vh + j * 4) = z;
    }
}

// ---------- main attention kernel ----------
extern __shared__ char smem[];

__global__ __launch_bounds__(NTH, 1)
void attn_kernel(const float* __restrict__ Q, float* __restrict__ out) {
    const int b = blockIdx.y;
    const int ncols = g_ccnt[b];
    const int nActive = (ncols + TR - 1) / TR;
    const int tid = threadIdx.x;

    // ---- zero-fill branch: masked rows ----
    if ((int)blockIdx.x >= nActive) {
        const int nmask = S - ncols;
        const int m0 = ((int)blockIdx.x - nActive) * TR;
        const int r = tid >> 4, tg = tid & 15;
        if (m0 + r >= nmask) return;
        const int row = g_midx[b][m0 + r];
        float4 z = {0.f, 0.f, 0.f, 0.f};
        float4* arow = (float4*)(out + (size_t)B * S * D + ((size_t)b * S + row) * S);
        #pragma unroll 8
        for (int it = 0; it < 32; it++) stcs4(arow + it * 16 + tg, z);
        stcs4((float4*)(out + ((size_t)b * S + row) * D + tg * 4), z);
        return;
    }

    const int row0c = blockIdx.x * TR;
    const int nrows = min(TR, ncols - row0c);
    const int lane = tid & 31, w = tid >> 5;
    const int rg = w >> 3, cg = w & 7;
    const int nt = (ncols + TC - 1) / TC;

    __half* sPh  = (__half*)(smem + OFF_PH);
    int*    sPinv= (int*)(smem + OFF_PINV);
    float*  sWsum= (float*)(smem + OFF_WSUM);
    float*  sInv = (float*)(smem + OFF_INV);
    int*    sOrig= (int*)(smem + OFF_ORIG);
    const uint32_t smemBase = (uint32_t)__cvta_generic_to_shared(smem);

    const __half* khB = g_kh + (size_t)b * S * D;
    const __half* vhB = g_vh + (size_t)b * S * D;

    // ---- phase-1 prologue: prefetch K tiles 0,1 ----
    {
        const int j = tid >> 2, c = (tid & 3) * 2;
        #pragma unroll
        for (int t = 0; t < 2; t++) {
            if (t < nt) {
                uint32_t stg = smemBase + OFF_STAGE + t * STG_STRIDE
                             + (uint32_t)((j * KP + c * 8) * 2);
                size_t gofs = (size_t)(t * TC + j) * D + c * 8;
                cpa16(stg, khB + gofs);
                cpa16(stg + 16, khB + gofs + 8);
            }
            cpcommit();
        }
    }

    if (tid < TR) sWsum[tid] = 0.f;
    ((int4*)sPinv)[tid] = ((const int4*)&g_pinv[b][0])[tid];

    // ---- Q load -> fp16 (pre-scaled by log2e/8) ----
    {
        int r = tid >> 4, f = tid & 15;
        float4 q = {0.f, 0.f, 0.f, 0.f};
        if (r < nrows) {
            int orig = g_cidx[b][row0c + r];
            if (f == 0) sOrig[r] = orig;
            q = ((const float4*)(Q + ((size_t)b * S + orig) * D))[f];
            q.x *= QSCALE; q.y *= QSCALE; q.z *= QSCALE; q.w *= QSCALE;
        }
        __half2* dh = (__half2*)(smem + OFF_QH + ((size_t)r * KP + f * 4) * 2);
        dh[0] = __floats2half2_rn(q.x, q.y);
        dh[1] = __floats2half2_rn(q.z, q.w);
    }
    __syncthreads();

    // ---- Q fragments to registers ----
    uint32_t qh[4][4];
    {
        const uint32_t aQoff =
            (uint32_t)(((rg * 16 + (lane & 15)) * KP + ((lane >> 4) << 3)) * 2);
        #pragma unroll
        for (int kk = 0; kk < 4; kk++)
            ldsm4(qh[kk][0], qh[kk][1], qh[kk][2], qh[kk][3],
                  smemBase + OFF_QH + aQoff + kk * 32);
    }

    const uint32_t bKoff =
        (uint32_t)(((cg * 16 + (lane & 7) + ((lane >> 4) << 3)) * KP
                    + (((lane >> 3) & 1) << 3)) * 2);
    const int rowE = rg * 16 + (lane >> 2);
    const int colE = cg * 16 + ((lane & 3) << 1);

    float sumLo = 0.f, sumHi = 0.f;

    // ================= PHASE 1: QK + deferred-exp pipeline ====================
    {
        float p0[4], p1[4];
        int cbPrev = 0;
        for (int i = 0; i < nt; i++) {
            const int ct = i * TC;
            const uint32_t stg = smemBase + OFF_STAGE + (uint32_t)((i % 3) * STG_STRIDE);
            cpwait1();
            __syncthreads();

            float c0[4] = {0.f, 0.f, 0.f, 0.f};
            float c1[4] = {0.f, 0.f, 0.f, 0.f};
            #pragma unroll
            for (int kk = 0; kk < 4; kk++) {
                uint32_t bh0, bh1, bh2, bh3;
                ldsm4(bh0, bh1, bh2, bh3, stg + bKoff + kk * 32);
                mma16816(c0, qh[kk][0], qh[kk][1], qh[kk][2], qh[kk][3], bh0, bh1);
                mma16816(c1, qh[kk][0], qh[kk][1], qh[kk][2], qh[kk][3], bh2, bh3);
            }
            if (i + 2 < nt) {
                const int j = tid >> 2, cch = (tid & 3) * 2;
                uint32_t sdst = smemBase + OFF_STAGE
                              + (uint32_t)(((i + 2) % 3) * STG_STRIDE)
                              + (uint32_t)((j * KP + cch * 8) * 2);
                size_t gofs = (size_t)((i + 2) * TC + j) * D + cch * 8;
                cpa16(sdst, khB + gofs);
                cpa16(sdst + 16, khB + gofs + 8);
            }
            cpcommit();
            if (i > 0) {
                const int cb = cbPrev;
                float e0 = (cb     < ncols) ? ex2(p0[0]) : 0.f;
                float e1 = (cb + 1 < ncols) ? ex2(p0[1]) : 0.f;
                float e2 = (cb     < ncols) ? ex2(p0[2]) : 0.f;
                float e3 = (cb + 1 < ncols) ? ex2(p0[3]) : 0.f;
                float e4 = (cb + 8 < ncols) ? ex2(p1[0]) : 0.f;
                float e5 = (cb + 9 < ncols) ? ex2(p1[1]) : 0.f;
                float e6 = (cb + 8 < ncols) ? ex2(p1[2]) : 0.f;
                float e7 = (cb + 9 < ncols) ? ex2(p1[3]) : 0.f;
                sumLo += (e0 + e1) + (e4 + e5);
                sumHi += (e2 + e3) + (e6 + e7);
                *(__half2*)&sPh[rowE * PP + cb]           = __floats2half2_rn(e0, e1);
                *(__half2*)&sPh[(rowE + 8) * PP + cb]     = __floats2half2_rn(e2, e3);
                *(__half2*)&sPh[rowE * PP + cb + 8]       = __floats2half2_rn(e4, e5);
                *(__half2*)&sPh[(rowE + 8) * PP + cb + 8] = __floats2half2_rn(e6, e7);
            }
            #pragma unroll
            for (int j = 0; j < 4; j++) { p0[j] = c0[j]; p1[j] = c1[j]; }
            cbPrev = ct + colE;
        }
        {
            const int cb = cbPrev;
            float e0 = (cb     < ncols) ? ex2(p0[0]) : 0.f;
            float e1 = (cb + 1 < ncols) ? ex2(p0[1]) : 0.f;
            float e2 = (cb     < ncols) ? ex2(p0[2]) : 0.f;
            float e3 = (cb + 1 < ncols) ? ex2(p0[3]) : 0.f;
            float e4 = (cb + 8 < ncols) ? ex2(p1[0]) : 0.f;
            float e5 = (cb + 9 < ncols) ? ex2(p1[1]) : 0.f;
            float e6 = (cb + 8 < ncols) ? ex2(p1[2]) : 0.f;
            float e7 = (cb + 9 < ncols) ? ex2(p1[3]) : 0.f;
            sumLo += (e0 + e1) + (e4 + e5);
            sumHi += (e2 + e3) + (e6 + e7);
            *(__half2*)&sPh[rowE * PP + cb]           = __floats2half2_rn(e0, e1);
            *(__half2*)&sPh[(rowE + 8) * PP + cb]     = __floats2half2_rn(e2, e3);
            *(__half2*)&sPh[rowE * PP + cb + 8]       = __floats2half2_rn(e4, e5);
            *(__half2*)&sPh[(rowE + 8) * PP + cb + 8] = __floats2half2_rn(e6, e7);
        }
    }

    // ---- row sums -> sInv ----
    sumLo += __shfl_xor_sync(0xffffffffu, sumLo, 1);
    sumLo += __shfl_xor_sync(0xffffffffu, sumLo, 2);
    sumHi += __shfl_xor_sync(0xffffffffu, sumHi, 1);
    sumHi += __shfl_xor_sync(0xffffffffu, sumHi, 2);
    if ((lane & 3) == 0) {
        atomicAdd(&sWsum[rowE], sumLo);
        atomicAdd(&sWsum[rowE + 8], sumHi);
    }
    __syncthreads();
    if (tid < TR) {
        float t = sWsum[tid];
        sInv[tid] = (t > 0.f) ? (1.f / t) : 0.f;
    }
    __syncthreads();

    // ================= PHASE 2: WB (shared pinv, both rows) then PV ============
    cpwait0();
    // V prologue: prefetch tiles 0,1 BEFORE the writeback
    {
        const int j = tid >> 2, c0 = (tid & 3) * 2;
        #pragma unroll
        for (int t = 0; t < 2; t++) {
            if (t < nt) {
                uint32_t stg = smemBase + OFF_STAGE + t * STG_STRIDE
                             + (uint32_t)((j * KP + c0 * 8) * 2);
                size_t gofs = (size_t)(t * TC + j) * D + c0 * 8;
                cpa16(stg, vhB + gofs);
                cpa16(stg + 16, vhB + gofs + 8);
            }
            cpcommit();
        }
    }

    // ---- attn writeback: 2 rows/warp, pinv loaded ONCE per column group ----
    {
        const int r0 = w * 2;
        const bool ok0 = (r0 < nrows), ok1 = (r0 + 1 < nrows);
        const float inv0 = ok0 ? sInv[r0] : 0.f;
        const float inv1 = ok1 ? sInv[r0 + 1] : 0.f;
        const __half* prow0 = &sPh[r0 * PP];
        const __half* prow1 = &sPh[(r0 + 1) * PP];
        float4* dst0 = ok0 ? (float4*)(out + (size_t)B * S * D
                                        + ((size_t)b * S + sOrig[r0]) * S) : nullptr;
        float4* dst1 = ok1 ? (float4*)(out + (size_t)B * S * D
                                        + ((size_t)b * S + sOrig[r0 + 1]) * S) : nullptr;
        if (ok0) {
            #pragma unroll 4
            for (int it = 0; it < 16; it++) {
                int cb = it * 32 + lane;
                int4 pv = ((const int4*)sPinv)[cb];
                // issue all 8 scalar gathers back-to-back (2 independent rows)
                float4 o0, o1;
                o0.x = (pv.x >= 0) ? __half2float(prow0[pv.x]) * inv0 : 0.f;
                o0.y = (pv.y >= 0) ? __half2float(prow0[pv.y]) * inv0 : 0.f;
                o0.z = (pv.z >= 0) ? __half2float(prow0[pv.z]) * inv0 : 0.f;
                o0.w = (pv.w >= 0) ? __half2float(prow0[pv.w]) * inv0 : 0.f;
                if (ok1) {
                    o1.x = (pv.x >= 0) ? __half2float(prow1[pv.x]) * inv1 : 0.f;
                    o1.y = (pv.y >= 0) ? __half2float(prow1[pv.y]) * inv1 : 0.f;
                    o1.z = (pv.z >= 0) ? __half2float(prow1[pv.z]) * inv1 : 0.f;
                    o1.w = (pv.w >= 0) ? __half2float(prow1[pv.w]) * inv1 : 0.f;
                }
                stcs4(dst0 + cb, o0);
                if (ok1) stcs4(dst1 + cb, o1);
            }
        }
    }

    // ---- PV: ALL 16 warps, one 16-row group x 8-col strip each ----
    {
        const uint32_t bVoff = (uint32_t)(((lane & 15) * KP + cg * 8) * 2);
        const uint32_t aP =
            (uint32_t)(((rg * 16 + (lane & 15)) * PP + ((lane >> 4) << 3)) * 2);
        const int colW = cg * 8 + ((lane & 3) << 1);

        float ctx[4] = {0.f, 0.f, 0.f, 0.f};

        for (int i = 0; i < nt; i++) {
            const int ct = i * TC;
            const uint32_t stg = smemBase + OFF_STAGE + (uint32_t)((i % 3) * STG_STRIDE);
            cpwait1();
            __syncthreads();
            #pragma unroll
            for (int ks = 0; ks < 8; ks++) {
                uint32_t a0, a1, a2, a3, b0, b1;
                ldsm2t(b0, b1, stg + bVoff + (uint32_t)(ks * 16 * KP * 2));
                ldsm4(a0, a1, a2, a3,
                      smemBase + OFF_PH + aP + (uint32_t)((ct + ks * 16) * 2));
                mma16816(ctx, a0, a1, a2, a3, b0, b1);
            }
            if (i + 2 < nt) {
                const int j = tid >> 2, c0 = (tid & 3) * 2;
                uint32_t sdst = smemBase + OFF_STAGE
                              + (uint32_t)(((i + 2) % 3) * STG_STRIDE)
                              + (uint32_t)((j * KP + c0 * 8) * 2);
                size_t gofs = (size_t)((i + 2) * TC + j) * D + c0 * 8;
                cpa16(sdst, vhB + gofs);
                cpa16(sdst + 16, vhB + gofs + 8);
            }
            cpcommit();
        }
        // ---- context write ----
        {
            const int r0 = rg * 16 + (lane >> 2);
            if (r0 < nrows) {
                float inv = sInv[r0];
                *(float2*)(out + ((size_t)b * S + sOrig[r0]) * D + colW) =
                    make_float2(ctx[0] * inv, ctx[1] * inv);
            }
            if (r0 + 8 < nrows) {
                float inv = sInv[r0 + 8];
                *(float2*)(out + ((size_t)b * S + sOrig[r0 + 8]) * D + colW) =
                    make_float2(ctx[2] * inv, ctx[3] * inv);
            }
        }
    }
}

extern "C" void kernel_launch(void* const* d_in, const int* in_sizes, int n_in,
                              void* d_out, int out_size) {
    const float* Q = (const float*)d_in[0];
    const float* K = (const float*)d_in[1];
    const float* V = (const float*)d_in[2];
    const void*  M = d_in[3];
    float* out = (float*)d_out;

    cudaFuncSetAttribute(attn_kernel, cudaFuncAttributeMaxDynamicSharedMemorySize,
                         SMEM_BYTES);

    build_mask_kernel<<<B, 256>>>(M);
    preprocess_k_kernel<<<dim3(S / 64, B), 256>>>(K);
    preprocess_v_kernel<<<dim3(S / 64, B), 256>>>(V);
    attn_kernel<<<dim3(S / TR + 1, B), NTH, SMEM_BYTES>>>(Q, out);
}